// round 7
// baseline (speedup 1.0000x reference)
#include <cuda_runtime.h>
#include <cuda_fp16.h>
#include <cstdint>

#define BH_NUM 64
#define S_LEN  2048
#define DHEAD  64

// 1/sqrt(64) * log2(e): scores computed directly in log2 domain
#define QSCALE 0.18033688011112042f

__device__ __forceinline__ unsigned packh2(float a, float b){
    __half2 h = __floats2half2_rn(a, b);
    return *reinterpret_cast<unsigned*>(&h);
}

// D = A*B + D,  m16n8k16 f16 inputs, fp32 accumulate
__device__ __forceinline__ void mma_f16(float c[4], const unsigned a[4],
                                        unsigned b0, unsigned b1){
    asm volatile(
        "mma.sync.aligned.m16n8k16.row.col.f32.f16.f16.f32 "
        "{%0,%1,%2,%3}, {%4,%5,%6,%7}, {%8,%9}, {%0,%1,%2,%3};\n"
        : "+f"(c[0]), "+f"(c[1]), "+f"(c[2]), "+f"(c[3])
        : "r"(a[0]), "r"(a[1]), "r"(a[2]), "r"(a[3]), "r"(b0), "r"(b1));
}

// Flash attention v6 (fp16 tensor path, exp2 softmax, MUFU/tensor interleave):
//  CTA = 128 q-rows, 4 warps x 32 rows (2 x 16-row tiles). KV tile = 64 keys.
//  Ks: K tile [key][d] f16, rows = 32 words (128B), word w stored at w ^ ((key&7)<<2).
//  Vs: V tile TRANSPOSED [dh][key] f16, word w at w ^ (((dh&7)<<2) ^ ((dh>>3)&3)).
//  P lives entirely in registers (f16 C-frag == A-frag layout).
//  softmax(rt1) exps are emitted inside the PV loop so MUFU overlaps tensor.
__global__ void __launch_bounds__(128, 2)
sdpa_flash_f16_v6(const float* __restrict__ Qg, const float* __restrict__ Kg,
                  const float* __restrict__ Vg, float* __restrict__ Og)
{
    __shared__ unsigned Ks[64*32];   // 8KB
    __shared__ unsigned Vs[64*32];   // 8KB

    const int tid  = threadIdx.x;
    const int w    = tid >> 5;
    const int lane = tid & 31;
    const int qg   = lane >> 2;      // 0..7
    const int rg   = lane & 3;       // 0..3
    const int swzA = qg << 2;

    const int qt = blockIdx.x;       // 0..15
    const int bh = blockIdx.y;       // 0..63

    const size_t base = (size_t)bh * S_LEN * DHEAD;

    // ---- stage Q tile (128x64 fp32 -> f16, QSCALE folded): rows 0..63 -> Ks, 64..127 -> Vs ----
    {
        const float4* Qt4 = (const float4*)(Qg + base + (size_t)qt*128*DHEAD);
        #pragma unroll
        for (int i = 0; i < 16; i++){
            int idx = tid + i*128;
            int row = idx >> 4;
            int c   = idx & 15;
            float4 v = Qt4[idx];
            unsigned* dst = (row < 64) ? Ks : Vs;
            int r = row & 63;
            int d = r*32 + ((2*c) ^ ((r & 7) << 2));
            uint2 p; p.x = packh2(v.x*QSCALE, v.y*QSCALE);
                     p.y = packh2(v.z*QSCALE, v.w*QSCALE);
            *(uint2*)&dst[d] = p;
        }
    }
    __syncthreads();

    // Q fragments: 2 row-tiles x 4 k-chunks x 4 regs (f16x2)
    unsigned qa[2][4][4];
    #pragma unroll
    for (int rt = 0; rt < 2; rt++){
        const int grow = w*32 + rt*16 + qg;
        const unsigned* src = (grow < 64) ? Ks : Vs;
        const int r0 = grow & 63;
        #pragma unroll
        for (int kc = 0; kc < 4; kc++){
            qa[rt][kc][0] = src[ r0    *32 + ((8*kc   + rg) ^ swzA)];
            qa[rt][kc][1] = src[(r0+8) *32 + ((8*kc   + rg) ^ swzA)];
            qa[rt][kc][2] = src[ r0    *32 + ((8*kc+4 + rg) ^ swzA)];
            qa[rt][kc][3] = src[(r0+8) *32 + ((8*kc+4 + rg) ^ swzA)];
        }
    }
    __syncthreads();

    float o[2][8][4];
    #pragma unroll
    for (int rt = 0; rt < 2; rt++)
        #pragma unroll
        for (int j = 0; j < 8; j++){ o[rt][j][0]=0.f; o[rt][j][1]=0.f; o[rt][j][2]=0.f; o[rt][j][3]=0.f; }
    float m0[2] = {-1e30f,-1e30f}, m1[2] = {-1e30f,-1e30f};
    float l0[2] = {0.f,0.f},       l1[2] = {0.f,0.f};

    const int vdh   = tid & 63;
    const int vgrp  = tid >> 6;
    const int vs_sw = ((vdh & 7) << 2) ^ ((vdh >> 3) & 3);

    for (int kt = 0; kt < S_LEN/64; kt++){
        // ---- fill K tile [key][d] (f16, swizzled) ----
        const float4* Kt4 = (const float4*)(Kg + base + (size_t)kt*64*DHEAD);
        #pragma unroll
        for (int i = 0; i < 8; i++){
            int idx = tid + i*128;
            int row = idx >> 4;
            int c   = idx & 15;
            float4 kv = Kt4[idx];
            int d = row*32 + ((2*c) ^ ((row & 7) << 2));
            uint2 p; p.x = packh2(kv.x, kv.y); p.y = packh2(kv.z, kv.w);
            *(uint2*)&Ks[d] = p;
        }
        // ---- fill V tile TRANSPOSED [dh][key] (f16, swizzled) ----
        {
            const float* Vt = Vg + base + (size_t)kt*64*DHEAD;
            #pragma unroll
            for (int i = 0; i < 8; i++){
                int k0 = vgrp*4 + i*8;
                float v0 = Vt[(k0+0)*64 + vdh];
                float v1 = Vt[(k0+1)*64 + vdh];
                float v2 = Vt[(k0+2)*64 + vdh];
                float v3 = Vt[(k0+3)*64 + vdh];
                Vs[vdh*32 + (((k0>>1)  ) ^ vs_sw)] = packh2(v0, v1);
                Vs[vdh*32 + (((k0>>1)+1) ^ vs_sw)] = packh2(v2, v3);
            }
        }
        __syncthreads();

        // ---- S = Q K^T (log2 domain) : each B load feeds both row-tiles ----
        float sc[2][8][4];
        #pragma unroll
        for (int rt = 0; rt < 2; rt++)
            #pragma unroll
            for (int j = 0; j < 8; j++){ sc[rt][j][0]=0.f; sc[rt][j][1]=0.f; sc[rt][j][2]=0.f; sc[rt][j][3]=0.f; }
        #pragma unroll
        for (int kc = 0; kc < 4; kc++){
            #pragma unroll
            for (int j = 0; j < 8; j++){
                const unsigned* kr = &Ks[(8*j + qg)*32];
                unsigned b0 = kr[(8*kc   + rg) ^ swzA];
                unsigned b1 = kr[(8*kc+4 + rg) ^ swzA];
                mma_f16(sc[0][j], qa[0][kc], b0, b1);
                mma_f16(sc[1][j], qa[1][kc], b0, b1);
            }
        }

        // ---- softmax rt0 (full) : max, exps -> pa0, rescale o0 ----
        unsigned pa0[4][4], pa1[4][4];
        {
            float tm0 = -1e30f, tm1 = -1e30f;
            #pragma unroll
            for (int j = 0; j < 8; j++){
                tm0 = fmaxf(tm0, fmaxf(sc[0][j][0], sc[0][j][1]));
                tm1 = fmaxf(tm1, fmaxf(sc[0][j][2], sc[0][j][3]));
            }
            tm0 = fmaxf(tm0, __shfl_xor_sync(0xffffffffu, tm0, 1));
            tm0 = fmaxf(tm0, __shfl_xor_sync(0xffffffffu, tm0, 2));
            tm1 = fmaxf(tm1, __shfl_xor_sync(0xffffffffu, tm1, 1));
            tm1 = fmaxf(tm1, __shfl_xor_sync(0xffffffffu, tm1, 2));
            float nm0 = fmaxf(m0[0], tm0), nm1 = fmaxf(m1[0], tm1);
            float al0 = exp2f(m0[0] - nm0), al1 = exp2f(m1[0] - nm1);
            m0[0] = nm0; m1[0] = nm1;

            float rs0 = 0.f, rs1 = 0.f;
            #pragma unroll
            for (int kc = 0; kc < 4; kc++){
                float e00 = exp2f(sc[0][2*kc  ][0] - nm0);
                float e01 = exp2f(sc[0][2*kc  ][1] - nm0);
                float e02 = exp2f(sc[0][2*kc  ][2] - nm1);
                float e03 = exp2f(sc[0][2*kc  ][3] - nm1);
                float e10 = exp2f(sc[0][2*kc+1][0] - nm0);
                float e11 = exp2f(sc[0][2*kc+1][1] - nm0);
                float e12 = exp2f(sc[0][2*kc+1][2] - nm1);
                float e13 = exp2f(sc[0][2*kc+1][3] - nm1);
                rs0 += e00 + e01 + e10 + e11;
                rs1 += e02 + e03 + e12 + e13;
                pa0[kc][0] = packh2(e00, e01);
                pa0[kc][1] = packh2(e02, e03);
                pa0[kc][2] = packh2(e10, e11);
                pa0[kc][3] = packh2(e12, e13);
            }
            #pragma unroll
            for (int j = 0; j < 8; j++){
                o[0][j][0]*=al0; o[0][j][1]*=al0; o[0][j][2]*=al1; o[0][j][3]*=al1;
            }
            rs0 += __shfl_xor_sync(0xffffffffu, rs0, 1);
            rs0 += __shfl_xor_sync(0xffffffffu, rs0, 2);
            rs1 += __shfl_xor_sync(0xffffffffu, rs1, 1);
            rs1 += __shfl_xor_sync(0xffffffffu, rs1, 2);
            l0[0] = l0[0]*al0 + rs0;
            l1[0] = l1[0]*al1 + rs1;
        }

        // ---- softmax rt1: max-reduction + o1 rescale only (exps go inside PV loop) ----
        float nm0b, nm1b;
        float rs0b = 0.f, rs1b = 0.f;
        {
            float tm0 = -1e30f, tm1 = -1e30f;
            #pragma unroll
            for (int j = 0; j < 8; j++){
                tm0 = fmaxf(tm0, fmaxf(sc[1][j][0], sc[1][j][1]));
                tm1 = fmaxf(tm1, fmaxf(sc[1][j][2], sc[1][j][3]));
            }
            tm0 = fmaxf(tm0, __shfl_xor_sync(0xffffffffu, tm0, 1));
            tm0 = fmaxf(tm0, __shfl_xor_sync(0xffffffffu, tm0, 2));
            tm1 = fmaxf(tm1, __shfl_xor_sync(0xffffffffu, tm1, 1));
            tm1 = fmaxf(tm1, __shfl_xor_sync(0xffffffffu, tm1, 2));
            nm0b = fmaxf(m0[1], tm0); nm1b = fmaxf(m1[1], tm1);
            float al0 = exp2f(m0[1] - nm0b), al1 = exp2f(m1[1] - nm1b);
            m0[1] = nm0b; m1[1] = nm1b;
            #pragma unroll
            for (int j = 0; j < 8; j++){
                o[1][j][0]*=al0; o[1][j][1]*=al0; o[1][j][2]*=al1; o[1][j][3]*=al1;
            }
            l0[1] *= al0; l1[1] *= al1;
        }

        // ---- PV loop: rt1 exps (MUFU) interleaved with PV mmas (tensor) ----
        #pragma unroll
        for (int kc = 0; kc < 4; kc++){
            // produce pa1[kc] right here: independent MUFU chain overlaps the mmas
            {
                float e00 = exp2f(sc[1][2*kc  ][0] - nm0b);
                float e01 = exp2f(sc[1][2*kc  ][1] - nm0b);
                float e02 = exp2f(sc[1][2*kc  ][2] - nm1b);
                float e03 = exp2f(sc[1][2*kc  ][3] - nm1b);
                float e10 = exp2f(sc[1][2*kc+1][0] - nm0b);
                float e11 = exp2f(sc[1][2*kc+1][1] - nm0b);
                float e12 = exp2f(sc[1][2*kc+1][2] - nm1b);
                float e13 = exp2f(sc[1][2*kc+1][3] - nm1b);
                rs0b += e00 + e01 + e10 + e11;
                rs1b += e02 + e03 + e12 + e13;
                pa1[kc][0] = packh2(e00, e01);
                pa1[kc][1] = packh2(e02, e03);
                pa1[kc][2] = packh2(e10, e11);
                pa1[kc][3] = packh2(e12, e13);
            }
            #pragma unroll
            for (int j = 0; j < 8; j++){
                const unsigned* vr = &Vs[(8*j + qg)*32];
                int vw = swzA ^ (j & 3);
                unsigned b0 = vr[(8*kc   + rg) ^ vw];
                unsigned b1 = vr[(8*kc+4 + rg) ^ vw];
                mma_f16(o[0][j], pa0[kc], b0, b1);
                mma_f16(o[1][j], pa1[kc], b0, b1);
            }
        }
        rs0b += __shfl_xor_sync(0xffffffffu, rs0b, 1);
        rs0b += __shfl_xor_sync(0xffffffffu, rs0b, 2);
        rs1b += __shfl_xor_sync(0xffffffffu, rs1b, 1);
        rs1b += __shfl_xor_sync(0xffffffffu, rs1b, 2);
        l0[1] += rs0b;
        l1[1] += rs1b;

        __syncthreads();   // protect Ks/Vs before next tile's fill
    }

    // ---- epilogue: O /= l, write fp32 ----
    float2* Od = (float2*)(Og + base);
    #pragma unroll
    for (int rt = 0; rt < 2; rt++){
        float inv0 = 1.f / l0[rt], inv1 = 1.f / l1[rt];
        const int row0 = qt*128 + w*32 + rt*16 + qg;
        #pragma unroll
        for (int j = 0; j < 8; j++){
            int d = j*8 + 2*rg;
            Od[( row0   *64 + d) >> 1] = make_float2(o[rt][j][0]*inv0, o[rt][j][1]*inv0);
            Od[((row0+8)*64 + d) >> 1] = make_float2(o[rt][j][2]*inv1, o[rt][j][3]*inv1);
        }
    }
}

extern "C" void kernel_launch(void* const* d_in, const int* in_sizes, int n_in,
                              void* d_out, int out_size){
    const float* Q = (const float*)d_in[0];
    const float* K = (const float*)d_in[1];
    const float* V = (const float*)d_in[2];
    float* O = (float*)d_out;
    dim3 grid(S_LEN/128, BH_NUM);   // q-tile fastest -> same-bh CTAs share K/V in L2
    sdpa_flash_f16_v6<<<grid, 128>>>(Q, K, V, O);
}